// round 1
// baseline (speedup 1.0000x reference)
#include <cuda_runtime.h>

// RKN scan: B=128 batches, T=128 steps, LOD=128, K=16, band BW=3 (7 diagonals).
// One CTA per batch element, 128 threads (one per latent row i).
// Banded tm tensors cached in shared memory as float4 (tm11,tm12,tm21,tm22).

#define NB   128
#define NT   128
#define NLOD 128
#define NK   16
#define ND   7      // band diagonals (2*BW+1)

static constexpr int TM4_FLOATS = NK * ND * NLOD * 4;   // 57344 floats = 229376 B
static constexpr int STATE_LEN  = 136;                  // 128 + 3 guard each side, padded
static constexpr int S_MU  = TM4_FLOATS;
static constexpr int S_ML  = S_MU + STATE_LEN;
static constexpr int S_CU  = S_ML + STATE_LEN;
static constexpr int S_CL  = S_CU + STATE_LEN;
static constexpr int S_CS  = S_CL + STATE_LEN;
static constexpr int S_RED = S_CS + STATE_LEN;          // 64 floats (16 k x 4 warps)
static constexpr int SMEM_FLOATS = S_RED + 64;
static constexpr int SMEM_BYTES  = SMEM_FLOATS * 4;     // 232352 <= 232448

#define RED_ROUND(m)                                                          \
  _Pragma("unroll")                                                           \
  for (int k = 0; k < (m); k++) {                                             \
    float a_ = v[k], c_ = v[k + (m)];                                         \
    bool  hi_ = (lane & (m)) != 0;                                            \
    float keep_ = hi_ ? c_ : a_;                                              \
    float send_ = hi_ ? a_ : c_;                                              \
    v[k] = keep_ + __shfl_xor_sync(0xffffffffu, send_, (m));                  \
  }

__global__ void __launch_bounds__(128, 1)
rkn_kernel(const float* __restrict__ lobs,   // (B,T,LOD)
           const float* __restrict__ ovars,  // (B,T,LOD)
           const float* __restrict__ imean,  // (B,2*LOD)
           const float* __restrict__ icu,    // (B,LOD)
           const float* __restrict__ icl,    // (B,LOD)
           const float* __restrict__ ics,    // (B,LOD)
           const float* __restrict__ tm11,   // (K,LOD,LOD)
           const float* __restrict__ tm12,
           const float* __restrict__ tm21,
           const float* __restrict__ tm22,
           const float* __restrict__ cw,     // (2*LOD, K)
           const float* __restrict__ cb,     // (K,)
           const float* __restrict__ tcu,    // (LOD,)
           const float* __restrict__ tcl,    // (LOD,)
           float* __restrict__ out)
{
    extern __shared__ float sm[];
    const int b    = blockIdx.x;
    const int tid  = threadIdx.x;
    const int lane = tid & 31;
    const int warp = tid >> 5;

    float4* tm4  = reinterpret_cast<float4*>(sm);
    float*  s_mu = sm + S_MU;
    float*  s_ml = sm + S_ML;
    float*  s_cu = sm + S_CU;
    float*  s_cl = sm + S_CL;
    float*  s_cs = sm + S_CS;
    float*  red  = sm + S_RED;

    // ---- prologue: band-extract tm into smem (masked; zeros at clipped edges)
    for (int r = tid; r < NK * NLOD; r += 128) {
        int k = r >> 7, i = r & 127;
        long base = ((long)k * NLOD + i) * NLOD;
        #pragma unroll
        for (int d = 0; d < ND; d++) {
            int j = i - 3 + d;
            float4 vv = make_float4(0.f, 0.f, 0.f, 0.f);
            if ((unsigned)j < (unsigned)NLOD) {
                vv.x = __ldg(tm11 + base + j);
                vv.y = __ldg(tm12 + base + j);
                vv.z = __ldg(tm21 + base + j);
                vv.w = __ldg(tm22 + base + j);
            }
            tm4[(k * ND + d) * NLOD + i] = vv;
        }
    }
    // zero guard cells of state arrays
    for (int idx = tid; idx < STATE_LEN; idx += 128) {
        s_mu[idx] = 0.f; s_ml[idx] = 0.f;
        s_cu[idx] = 0.f; s_cl[idx] = 0.f; s_cs[idx] = 0.f;
    }

    // ---- per-thread constants
    float Wu[NK], Wl[NK], bb[NK];
    #pragma unroll
    for (int k = 0; k < NK; k++) {
        Wu[k] = __ldg(cw + tid * NK + k);
        Wl[k] = __ldg(cw + (NLOD + tid) * NK + k);
        bb[k] = __ldg(cb + k);
    }
    const float tcur = __ldg(tcu + tid);
    const float tclr = __ldg(tcl + tid);

    // carry state in registers (this thread's row)
    float pmU = imean[(long)b * 2 * NLOD + tid];
    float pmL = imean[(long)b * 2 * NLOD + NLOD + tid];
    float cU  = icu[(long)b * NLOD + tid];
    float cL  = icl[(long)b * NLOD + tid];
    float cS  = ics[(long)b * NLOD + tid];

    float* out_pm = out;
    float* out_cu = out + (long)NB * NT * 2 * NLOD;
    float* out_cl = out_cu + (long)NB * NT * NLOD;
    float* out_cs = out_cl + (long)NB * NT * NLOD;

    float obs_r = __ldg(lobs  + ((long)b * NT) * NLOD + tid);
    float ov_r  = __ldg(ovars + ((long)b * NT) * NLOD + tid);

    __syncthreads();

    for (int t = 0; t < NT; t++) {
        // ---- observation update (elementwise)
        float denom = cU + ov_r;
        float rd    = 1.0f / denom;
        float qu    = cU * rd;
        float ql    = cS * rd;
        float res   = obs_r - pmU;
        float pu    = pmU + qu * res;
        float pl    = pmL + ql * res;
        float cf    = 1.0f - qu;
        float pcu   = cf * cU;
        float pcl   = cL - ql * cS;
        float pcs   = cf * cS;

        // prefetch next step's observations (latency hidden behind this step)
        if (t + 1 < NT) {
            obs_r = __ldg(lobs  + ((long)b * NT + t + 1) * NLOD + tid);
            ov_r  = __ldg(ovars + ((long)b * NT + t + 1) * NLOD + tid);
        }

        // publish post state for neighbor reads
        s_mu[3 + tid] = pu;  s_ml[3 + tid] = pl;
        s_cu[3 + tid] = pcu; s_cl[3 + tid] = pcl; s_cs[3 + tid] = pcs;

        // write outputs (post_mean, pcu, pcl, pcs)
        long obase = (long)b * NT + t;
        out_pm[obase * 2 * NLOD + tid]        = pu;
        out_pm[obase * 2 * NLOD + NLOD + tid] = pl;
        out_cu[obase * NLOD + tid] = pcu;
        out_cl[obase * NLOD + tid] = pcl;
        out_cs[obase * NLOD + tid] = pcs;

        // ---- logits: v[k] = pu*W[i,k] + pl*W[128+i,k], reduced over 128 rows
        float v[NK];
        #pragma unroll
        for (int k = 0; k < NK; k++) v[k] = fmaf(pu, Wu[k], pl * Wl[k]);
        // fold upper half-warp onto lower
        #pragma unroll
        for (int k = 0; k < NK; k++) v[k] += __shfl_xor_sync(0xffffffffu, v[k], 16);
        // value-splitting butterfly: after these rounds lane L holds sum for k = L&15
        RED_ROUND(8)
        RED_ROUND(4)
        RED_ROUND(2)
        RED_ROUND(1)
        if (lane < 16) red[lane * 4 + warp] = v[0];
        __syncthreads();

        // ---- softmax (computed redundantly by every thread; avoids 2nd barrier)
        float lg[NK];
        const float4* red4 = reinterpret_cast<const float4*>(red);
        #pragma unroll
        for (int k = 0; k < NK; k++) {
            float4 p = red4[k];
            lg[k] = bb[k] + ((p.x + p.y) + (p.z + p.w));
        }
        float mx = lg[0];
        #pragma unroll
        for (int k = 1; k < NK; k++) mx = fmaxf(mx, lg[k]);
        float ssum = 0.f;
        #pragma unroll
        for (int k = 0; k < NK; k++) { lg[k] = __expf(lg[k] - mx); ssum += lg[k]; }
        float inv = 1.0f / ssum;

        // ---- A-generation: band rows of A11,A12,A21,A22 for row i = tid
        float A11[ND] = {}, A12[ND] = {}, A21[ND] = {}, A22[ND] = {};
        #pragma unroll
        for (int k = 0; k < NK; k++) {
            float a = lg[k] * inv;
            const float4* p = tm4 + k * ND * NLOD + tid;
            #pragma unroll
            for (int d = 0; d < ND; d++) {
                float4 tv = p[d * NLOD];
                A11[d] = fmaf(a, tv.x, A11[d]);
                A12[d] = fmaf(a, tv.y, A12[d]);
                A21[d] = fmaf(a, tv.z, A21[d]);
                A22[d] = fmaf(a, tv.w, A22[d]);
            }
        }
        A11[3] += 1.0f;   // + I
        A22[3] += 1.0f;

        // ---- banded matvec: predicted mean + covariance
        float nmu = 0.f, nml = 0.f, ncu = 0.f, ncl = 0.f, ncs = 0.f;
        #pragma unroll
        for (int d = 0; d < ND; d++) {
            int j = tid + d;   // smem index of global column i-3+d (guard offset +3)
            float muj = s_mu[j], mlj = s_ml[j];
            float cuj = s_cu[j], clj = s_cl[j], csj = s_cs[j];
            float p11 = A11[d], p12 = A12[d], p21 = A21[d], p22 = A22[d];
            nmu = fmaf(p11, muj, nmu); nmu = fmaf(p12, mlj, nmu);
            nml = fmaf(p21, muj, nml); nml = fmaf(p22, mlj, nml);
            ncu = fmaf(p11 * p11, cuj, ncu);
            ncu = fmaf(2.0f * p11 * p12, csj, ncu);
            ncu = fmaf(p12 * p12, clj, ncu);
            ncl = fmaf(p21 * p21, cuj, ncl);
            ncl = fmaf(2.0f * p21 * p22, csj, ncl);
            ncl = fmaf(p22 * p22, clj, ncl);
            ncs = fmaf(p21 * p11, cuj, ncs);
            ncs = fmaf(fmaf(p22, p11, p21 * p12), csj, ncs);
            ncs = fmaf(p22 * p12, clj, ncs);
        }
        pmU = nmu; pmL = nml;
        cU = ncu + tcur; cL = ncl + tclr; cS = ncs;
        __syncthreads();   // protect state arrays before next step overwrites
    }
}

extern "C" void kernel_launch(void* const* d_in, const int* in_sizes, int n_in,
                              void* d_out, int out_size)
{
    (void)in_sizes; (void)n_in; (void)out_size;
    const float* lobs  = (const float*)d_in[0];
    const float* ovars = (const float*)d_in[1];
    const float* imean = (const float*)d_in[2];
    const float* icu   = (const float*)d_in[3];
    const float* icl   = (const float*)d_in[4];
    const float* ics   = (const float*)d_in[5];
    const float* tm11  = (const float*)d_in[6];
    const float* tm12  = (const float*)d_in[7];
    const float* tm21  = (const float*)d_in[8];
    const float* tm22  = (const float*)d_in[9];
    const float* cw    = (const float*)d_in[10];
    const float* cb    = (const float*)d_in[11];
    const float* tcu   = (const float*)d_in[12];
    const float* tcl   = (const float*)d_in[13];
    float* out = (float*)d_out;

    cudaFuncSetAttribute(rkn_kernel,
                         cudaFuncAttributeMaxDynamicSharedMemorySize, SMEM_BYTES);

    rkn_kernel<<<NB, 128, SMEM_BYTES>>>(lobs, ovars, imean, icu, icl, ics,
                                        tm11, tm12, tm21, tm22,
                                        cw, cb, tcu, tcl, out);
}

// round 2
// speedup vs baseline: 1.0837x; 1.0837x over previous
#include <cuda_runtime.h>
#include <cuda_bf16.h>

// RKN scan, R2: bf16-packed off-diagonal tm planes (fp32 diagonal plane),
// 256 threads/CTA (two threads per row, diagonal-set split), FFMA2 A-gen.
// One CTA per batch element; tm cached in smem, reused across 128 steps.

#define NB   128
#define NT   128
#define NLOD 128
#define NK   16

// ---- dynamic smem layout (byte offsets) ----
static constexpr int OD_OFF    = 0;                      // uint4[NK*3*NLOD] bf16 pairs
static constexpr int OD_BYTES  = NK * 3 * NLOD * 16;     // 98304
static constexpr int DG_OFF    = OD_OFF + OD_BYTES;      // float4[NK*NLOD] fp32 diag
static constexpr int DG_BYTES  = NK * NLOD * 16;         // 32768
static constexpr int STATE_LEN = 136;                    // 128 + 3 guards each side
static constexpr int S_MU      = DG_OFF + DG_BYTES;      // 131072
static constexpr int S_ML      = S_MU + STATE_LEN * 4;
static constexpr int S_CU      = S_ML + STATE_LEN * 4;
static constexpr int S_CL      = S_CU + STATE_LEN * 4;
static constexpr int S_CS      = S_CL + STATE_LEN * 4;
static constexpr int S_RED     = S_CS + STATE_LEN * 4;   // 64 floats
static constexpr int S_P4      = S_RED + 256;            // float4[128] partials
static constexpr int S_P1      = S_P4 + 2048;            // float[128]  partials
static constexpr int SMEM_BYTES = S_P1 + 512;            // 136608 <= 227KB

// pack two floats -> one u32 of two bf16 (a in low16, b in high16)
__device__ __forceinline__ unsigned int pk(float a, float b) {
    __nv_bfloat162 t = __floats2bfloat162_rn(a, b);
    return reinterpret_cast<unsigned int&>(t);
}
// unpack u32 (bf16 pair) -> packed f32x2 (low bf16 -> .lo float, high -> .hi)
__device__ __forceinline__ unsigned long long bf2f2(unsigned int p) {
    unsigned long long r;
    asm("{\n\t.reg .b32 l,h;\n\t"
        "shl.b32 l, %1, 16;\n\t"
        "and.b32 h, %1, 0xFFFF0000;\n\t"
        "mov.b64 %0, {l,h};\n\t}" : "=l"(r) : "r"(p));
    return r;
}
__device__ __forceinline__ void ffma2(unsigned long long& acc,
                                      unsigned long long x,
                                      unsigned long long a2) {
    asm("fma.rn.f32x2 %0, %1, %2, %0;" : "+l"(acc) : "l"(x), "l"(a2));
}
__device__ __forceinline__ unsigned long long dup2(float a) {
    unsigned long long r;
    asm("mov.b64 %0, {%1, %1};" : "=l"(r) : "f"(a));
    return r;
}
__device__ __forceinline__ void unpk2(unsigned long long r, float& x, float& y) {
    asm("mov.b64 {%0, %1}, %2;" : "=f"(x), "=f"(y) : "l"(r));
}

#define RED_ROUND(m)                                                          \
  _Pragma("unroll")                                                           \
  for (int k = 0; k < (m); k++) {                                             \
    float a_ = v[k], c_ = v[k + (m)];                                         \
    bool  hi_ = (lane & (m)) != 0;                                            \
    float keep_ = hi_ ? c_ : a_;                                              \
    float send_ = hi_ ? a_ : c_;                                              \
    v[k] = keep_ + __shfl_xor_sync(0xffffffffu, send_, (m));                  \
  }

// accumulate the matvec partial contribution of one diagonal d
#define BAND_ACC(d, a11, a12, a21, a22)                                       \
  {                                                                           \
    int j_ = i + (d);                                                         \
    float muj = s_mu[j_], mlj = s_ml[j_];                                     \
    float cuj = s_cu[j_], clj = s_cl[j_], csj = s_cs[j_];                     \
    nmu = fmaf((a11), muj, nmu); nmu = fmaf((a12), mlj, nmu);                 \
    nml = fmaf((a21), muj, nml); nml = fmaf((a22), mlj, nml);                 \
    ncu = fmaf((a11) * (a11), cuj, ncu);                                      \
    ncu = fmaf(2.0f * (a11) * (a12), csj, ncu);                               \
    ncu = fmaf((a12) * (a12), clj, ncu);                                      \
    ncl = fmaf((a21) * (a21), cuj, ncl);                                      \
    ncl = fmaf(2.0f * (a21) * (a22), csj, ncl);                               \
    ncl = fmaf((a22) * (a22), clj, ncl);                                      \
    ncs = fmaf((a21) * (a11), cuj, ncs);                                      \
    ncs = fmaf(fmaf((a22), (a11), (a21) * (a12)), csj, ncs);                  \
    ncs = fmaf((a22) * (a12), clj, ncs);                                      \
  }

__global__ void __launch_bounds__(256, 1)
rkn_kernel(const float* __restrict__ lobs,   // (B,T,LOD)
           const float* __restrict__ ovars,  // (B,T,LOD)
           const float* __restrict__ imean,  // (B,2*LOD)
           const float* __restrict__ icu,
           const float* __restrict__ icl,
           const float* __restrict__ ics,
           const float* __restrict__ tm11,   // (K,LOD,LOD)
           const float* __restrict__ tm12,
           const float* __restrict__ tm21,
           const float* __restrict__ tm22,
           const float* __restrict__ cw,     // (2*LOD, K)
           const float* __restrict__ cb,     // (K,)
           const float* __restrict__ tcu,
           const float* __restrict__ tcl,
           float* __restrict__ out)
{
    extern __shared__ char smraw[];
    const int b    = blockIdx.x;
    const int tid  = threadIdx.x;
    const int lane = tid & 31;
    const int warp = tid >> 5;
    const int i    = tid & 127;   // row
    const int h    = tid >> 7;    // which half of the d-split

    uint4*  od   = reinterpret_cast<uint4*>(smraw + OD_OFF);
    float4* dg   = reinterpret_cast<float4*>(smraw + DG_OFF);
    float*  s_mu = reinterpret_cast<float*>(smraw + S_MU);
    float*  s_ml = reinterpret_cast<float*>(smraw + S_ML);
    float*  s_cu = reinterpret_cast<float*>(smraw + S_CU);
    float*  s_cl = reinterpret_cast<float*>(smraw + S_CL);
    float*  s_cs = reinterpret_cast<float*>(smraw + S_CS);
    float*  red  = reinterpret_cast<float*>(smraw + S_RED);
    float4* p4   = reinterpret_cast<float4*>(smraw + S_P4);
    float*  p1   = reinterpret_cast<float*>(smraw + S_P1);

    // ---- prologue: band-extract tm, pack off-diags to bf16, diag fp32 ----
    for (int r = tid; r < NK * NLOD; r += 256) {
        int k = r >> 7, ii = r & 127;
        long base = ((long)k * NLOD + ii) * NLOD;
        float m11[7], m12[7], m21[7], m22[7];
        #pragma unroll
        for (int d = 0; d < 7; d++) {
            int j = ii - 3 + d;
            if ((unsigned)j < (unsigned)NLOD) {
                m11[d] = __ldg(tm11 + base + j);
                m12[d] = __ldg(tm12 + base + j);
                m21[d] = __ldg(tm21 + base + j);
                m22[d] = __ldg(tm22 + base + j);
            } else {
                m11[d] = 0.f; m12[d] = 0.f; m21[d] = 0.f; m22[d] = 0.f;
            }
        }
        dg[k * NLOD + ii] = make_float4(m11[3], m12[3], m21[3], m22[3]);
        // pair 0: (d4, d5)  pair 1: (d6, d2)  pair 2: (d0, d1)
        od[(k * 3 + 0) * NLOD + ii] = make_uint4(pk(m11[4], m12[4]), pk(m21[4], m22[4]),
                                                 pk(m11[5], m12[5]), pk(m21[5], m22[5]));
        od[(k * 3 + 1) * NLOD + ii] = make_uint4(pk(m11[6], m12[6]), pk(m21[6], m22[6]),
                                                 pk(m11[2], m12[2]), pk(m21[2], m22[2]));
        od[(k * 3 + 2) * NLOD + ii] = make_uint4(pk(m11[0], m12[0]), pk(m21[0], m22[0]),
                                                 pk(m11[1], m12[1]), pk(m21[1], m22[1]));
    }
    for (int idx = tid; idx < STATE_LEN; idx += 256) {
        s_mu[idx] = 0.f; s_ml[idx] = 0.f;
        s_cu[idx] = 0.f; s_cl[idx] = 0.f; s_cs[idx] = 0.f;
    }

    // per-thread constants
    float bb[NK];
    #pragma unroll
    for (int k = 0; k < NK; k++) bb[k] = __ldg(cb + k);

    float Wu[NK], Wl[NK];
    float tcur = 0.f, tclr = 0.f;
    float pmU = 0.f, pmL = 0.f, cU = 0.f, cL = 0.f, cS = 0.f;
    float obs_r = 0.f, ov_r = 0.f;
    if (h == 0) {
        #pragma unroll
        for (int k = 0; k < NK; k++) {
            Wu[k] = __ldg(cw + i * NK + k);
            Wl[k] = __ldg(cw + (NLOD + i) * NK + k);
        }
        tcur = __ldg(tcu + i);
        tclr = __ldg(tcl + i);
        pmU = imean[(long)b * 2 * NLOD + i];
        pmL = imean[(long)b * 2 * NLOD + NLOD + i];
        cU  = icu[(long)b * NLOD + i];
        cL  = icl[(long)b * NLOD + i];
        cS  = ics[(long)b * NLOD + i];
        obs_r = __ldg(lobs  + ((long)b * NT) * NLOD + i);
        ov_r  = __ldg(ovars + ((long)b * NT) * NLOD + i);
    }

    float* out_pm = out;
    float* out_cu = out + (long)NB * NT * 2 * NLOD;
    float* out_cl = out_cu + (long)NB * NT * NLOD;
    float* out_cs = out_cl + (long)NB * NT * NLOD;

    __syncthreads();

    for (int t = 0; t < NT; t++) {
        if (h == 0) {
            // ---- observation update ----
            float denom = cU + ov_r;
            float rd    = 1.0f / denom;
            float qu    = cU * rd;
            float ql    = cS * rd;
            float res   = obs_r - pmU;
            float pu    = pmU + qu * res;
            float pl    = pmL + ql * res;
            float cf    = 1.0f - qu;
            float pcu   = cf * cU;
            float pcl   = cL - ql * cS;
            float pcs   = cf * cS;

            if (t + 1 < NT) {
                obs_r = __ldg(lobs  + ((long)b * NT + t + 1) * NLOD + i);
                ov_r  = __ldg(ovars + ((long)b * NT + t + 1) * NLOD + i);
            }

            s_mu[3 + i] = pu;  s_ml[3 + i] = pl;
            s_cu[3 + i] = pcu; s_cl[3 + i] = pcl; s_cs[3 + i] = pcs;

            long obase = (long)b * NT + t;
            out_pm[obase * 2 * NLOD + i]        = pu;
            out_pm[obase * 2 * NLOD + NLOD + i] = pl;
            out_cu[obase * NLOD + i] = pcu;
            out_cl[obase * NLOD + i] = pcl;
            out_cs[obase * NLOD + i] = pcs;

            // ---- logits reduction over rows ----
            float v[NK];
            #pragma unroll
            for (int k = 0; k < NK; k++) v[k] = fmaf(pu, Wu[k], pl * Wl[k]);
            #pragma unroll
            for (int k = 0; k < NK; k++) v[k] += __shfl_xor_sync(0xffffffffu, v[k], 16);
            RED_ROUND(8)
            RED_ROUND(4)
            RED_ROUND(2)
            RED_ROUND(1)
            if (lane < 16) red[lane * 4 + warp] = v[0];
        }
        __syncthreads();

        // ---- softmax weights (redundant in every thread) ----
        float lg[NK];
        {
            const float4* red4 = reinterpret_cast<const float4*>(red);
            #pragma unroll
            for (int k = 0; k < NK; k++) {
                float4 p = red4[k];
                lg[k] = bb[k] + ((p.x + p.y) + (p.z + p.w));
            }
            float mx = lg[0];
            #pragma unroll
            for (int k = 1; k < NK; k++) mx = fmaxf(mx, lg[k]);
            float ssum = 0.f;
            #pragma unroll
            for (int k = 0; k < NK; k++) { lg[k] = __expf(lg[k] - mx); ssum += lg[k]; }
            float inv = 1.0f / ssum;
            #pragma unroll
            for (int k = 0; k < NK; k++) lg[k] *= inv;   // fold later scale via mult here
        }

        float nmu = 0.f, nml = 0.f, ncu = 0.f, ncl = 0.f, ncs = 0.f;

        if (h == 0) {
            // ---- A-gen for d in {0,1,3}; diag (d=3) in fp32 ----
            unsigned long long P0 = 0ull, Q0 = 0ull, P1 = 0ull, Q1 = 0ull;
            float D11 = 0.f, D12 = 0.f, D21 = 0.f, D22 = 0.f;
            #pragma unroll
            for (int k = 0; k < NK; k++) {
                uint4  v  = od[(k * 3 + 2) * NLOD + i];
                float4 g  = dg[k * NLOD + i];
                float  a  = lg[k];
                unsigned long long a2 = dup2(a);
                ffma2(P0, bf2f2(v.x), a2);
                ffma2(Q0, bf2f2(v.y), a2);
                ffma2(P1, bf2f2(v.z), a2);
                ffma2(Q1, bf2f2(v.w), a2);
                D11 = fmaf(a, g.x, D11);
                D12 = fmaf(a, g.y, D12);
                D21 = fmaf(a, g.z, D21);
                D22 = fmaf(a, g.w, D22);
            }
            float a11, a12, a21, a22;
            unpk2(P0, a11, a12); unpk2(Q0, a21, a22);
            BAND_ACC(0, a11, a12, a21, a22)
            unpk2(P1, a11, a12); unpk2(Q1, a21, a22);
            BAND_ACC(1, a11, a12, a21, a22)
            BAND_ACC(3, D11 + 1.0f, D12, D21, D22 + 1.0f)
        } else {
            // ---- A-gen for d in {4,5,6,2} ----
            unsigned long long P4 = 0ull, Q4 = 0ull, P5 = 0ull, Q5 = 0ull;
            unsigned long long P6 = 0ull, Q6 = 0ull, P2 = 0ull, Q2 = 0ull;
            #pragma unroll
            for (int k = 0; k < NK; k++) {
                uint4 va = od[(k * 3 + 0) * NLOD + i];   // (d4, d5)
                uint4 vb = od[(k * 3 + 1) * NLOD + i];   // (d6, d2)
                unsigned long long a2 = dup2(lg[k]);
                ffma2(P4, bf2f2(va.x), a2);
                ffma2(Q4, bf2f2(va.y), a2);
                ffma2(P5, bf2f2(va.z), a2);
                ffma2(Q5, bf2f2(va.w), a2);
                ffma2(P6, bf2f2(vb.x), a2);
                ffma2(Q6, bf2f2(vb.y), a2);
                ffma2(P2, bf2f2(vb.z), a2);
                ffma2(Q2, bf2f2(vb.w), a2);
            }
            float a11, a12, a21, a22;
            unpk2(P2, a11, a12); unpk2(Q2, a21, a22);
            BAND_ACC(2, a11, a12, a21, a22)
            unpk2(P4, a11, a12); unpk2(Q4, a21, a22);
            BAND_ACC(4, a11, a12, a21, a22)
            unpk2(P5, a11, a12); unpk2(Q5, a21, a22);
            BAND_ACC(5, a11, a12, a21, a22)
            unpk2(P6, a11, a12); unpk2(Q6, a21, a22);
            BAND_ACC(6, a11, a12, a21, a22)
            p4[i] = make_float4(nmu, nml, ncu, ncl);
            p1[i] = ncs;
        }
        __syncthreads();

        if (h == 0) {
            float4 pp = p4[i];
            pmU = nmu + pp.x;
            pmL = nml + pp.y;
            cU  = ncu + pp.z + tcur;
            cL  = ncl + pp.w + tclr;
            cS  = ncs + p1[i];
        }
    }
}

extern "C" void kernel_launch(void* const* d_in, const int* in_sizes, int n_in,
                              void* d_out, int out_size)
{
    (void)in_sizes; (void)n_in; (void)out_size;
    const float* lobs  = (const float*)d_in[0];
    const float* ovars = (const float*)d_in[1];
    const float* imean = (const float*)d_in[2];
    const float* icu   = (const float*)d_in[3];
    const float* icl   = (const float*)d_in[4];
    const float* ics   = (const float*)d_in[5];
    const float* tm11  = (const float*)d_in[6];
    const float* tm12  = (const float*)d_in[7];
    const float* tm21  = (const float*)d_in[8];
    const float* tm22  = (const float*)d_in[9];
    const float* cw    = (const float*)d_in[10];
    const float* cb    = (const float*)d_in[11];
    const float* tcu   = (const float*)d_in[12];
    const float* tcl   = (const float*)d_in[13];
    float* out = (float*)d_out;

    cudaFuncSetAttribute(rkn_kernel,
                         cudaFuncAttributeMaxDynamicSharedMemorySize, SMEM_BYTES);

    rkn_kernel<<<NB, 256, SMEM_BYTES>>>(lobs, ovars, imean, icu, icl, ics,
                                        tm11, tm12, tm21, tm22,
                                        cw, cb, tcu, tcl, out);
}